// round 16
// baseline (speedup 1.0000x reference)
#include <cuda_runtime.h>
#include <cuda_bf16.h>
#include <stdint.h>
#include <math.h>
#include <float.h>

#define NN 100000
#define NE 1600000
#define DIM 128
#define NL 3
#define NG 256
#define MT 64                            // GEMM M-tile rows
#define NBLK2 ((NN + MT - 1) / MT)       // 1563
#define GGRID 296                        // persistent GEMM grid: 2 CTAs/SM x 148

// padded smem rows: 272 bytes (136 bf16)
#define ROWB 272
#define SB_HI 0                          // B hi/lo: persistent, 68KB
#define SB_LO 34816
#define SA_HI 69632                      // A hi/lo: per-tile, 34KB
#define SA_LO 87040
#define DSMEM 104448                     // 2 CTAs/SM

// ---------------- scratch (static device globals; zero-initialized) ----------------
__device__ __align__(16) float g_X[(size_t)NN * DIM];                 // layer output fp32
__device__ __align__(16) float g_Y[(size_t)NN * DIM];                 // post-GEMM1 pre-BN fp32
__device__ __align__(16) unsigned short g_Hh[(size_t)NN * DIM];       // agg bf16 hi, row-major
__device__ __align__(16) unsigned short g_Hl[(size_t)NN * DIM];       // agg bf16 lo
__device__ __align__(16) unsigned short g_Wth[6 * DIM * DIM];         // W^T bf16 hi [mat][n][k]
__device__ __align__(16) unsigned short g_Wtl[6 * DIM * DIM];
__device__ int   g_rowptr[NN + 1];
__device__ int   g_deg[NN];
__device__ int   g_cur[NN];
__device__ int   g_col[NE];
__device__ float g_stats[2 * DIM];       // zeroed by k_agg block 0 before each GEMM1
__device__ __align__(16) float g_pool[NG * 2 * DIM];
__device__ int   g_gstart[NG + 1];

__device__ __forceinline__ uint32_t smem_u32(const void* p) {
    uint32_t a;
    asm("{ .reg .u64 t; cvta.to.shared.u64 t, %1; cvt.u32.u64 %0, t; }" : "=r"(a) : "l"(p));
    return a;
}
__device__ __forceinline__ void ldm4(uint32_t* r, uint32_t a) {
    asm volatile("ldmatrix.sync.aligned.m8n8.x4.shared.b16 {%0,%1,%2,%3}, [%4];"
                 : "=r"(r[0]), "=r"(r[1]), "=r"(r[2]), "=r"(r[3]) : "r"(a));
}
__device__ __forceinline__ void mma_bf16(float* c, const uint32_t* a, const uint32_t* b) {
    asm volatile(
        "mma.sync.aligned.m16n8k16.row.col.f32.bf16.bf16.f32 "
        "{%0,%1,%2,%3}, {%4,%5,%6,%7}, {%8,%9}, {%0,%1,%2,%3};"
        : "+f"(c[0]), "+f"(c[1]), "+f"(c[2]), "+f"(c[3])
        : "r"(a[0]), "r"(a[1]), "r"(a[2]), "r"(a[3]), "r"(b[0]), "r"(b[1]));
}
__device__ __forceinline__ void cpa16(uint32_t dst, const void* src) {
    asm volatile("cp.async.cg.shared.global [%0], [%1], 16;" :: "r"(dst), "l"(src));
}
__device__ __forceinline__ void cpa16z(uint32_t dst, const void* src, int sz) {
    asm volatile("cp.async.cg.shared.global [%0], [%1], 16, %2;" :: "r"(dst), "l"(src), "r"(sz));
}
#define CP_COMMIT() asm volatile("cp.async.commit_group;" ::: "memory")
#define CP_WAIT0()  asm volatile("cp.async.wait_group 0;" ::: "memory")

// ---------------- CSR build ----------------
__global__ void k_zero_csr() {
    int i = blockIdx.x * blockDim.x + threadIdx.x;
    if (i < NN) { g_deg[i] = 0; g_cur[i] = 0; }
}
__global__ void k_hist(const int* __restrict__ ei) {
    int e = blockIdx.x * blockDim.x + threadIdx.x;
    if (e < NE) atomicAdd(&g_deg[ei[NE + e]], 1);
}
__global__ void k_scan() {
    __shared__ int part[1024];
    int t = threadIdx.x;
    const int C = (NN + 1023) / 1024;
    int beg = t * C, end = min(beg + C, NN);
    int s = 0;
    for (int i = beg; i < end; i++) s += g_deg[i];
    part[t] = s;
    __syncthreads();
    for (int d = 1; d < 1024; d <<= 1) {
        int v = (t >= d) ? part[t - d] : 0;
        __syncthreads();
        part[t] += v;
        __syncthreads();
    }
    int off = (t == 0) ? 0 : part[t - 1];
    for (int i = beg; i < end; i++) { g_rowptr[i] = off; off += g_deg[i]; }
    if (t == 1023) g_rowptr[NN] = part[1023];
}
__global__ void k_fill(const int* __restrict__ ei) {
    int e = blockIdx.x * blockDim.x + threadIdx.x;
    if (e < NE) {
        int s = ei[e];
        int d = ei[NE + e];
        g_col[g_rowptr[d] + atomicAdd(&g_cur[d], 1)] = s;
    }
}

// ---------------- weight split: W^T -> bf16 hi/lo row-major [n][k] ----------------
__global__ void k_wsplit(const float* __restrict__ W1, const float* __restrict__ W2) {
    int idx = blockIdx.x * blockDim.x + threadIdx.x;
    if (idx >= 6 * DIM * DIM) return;
    int mat = idx >> 14;
    int e = idx & 16383;
    int n = e >> 7, k = e & 127;
    int l = mat >> 1;
    const float* W = (mat & 1) ? W2 : W1;
    float v = W[(size_t)l * DIM * DIM + k * DIM + n];   // B[n][k] = W[k][n]
    __nv_bfloat16 h = __float2bfloat16_rn(v);
    __nv_bfloat16 lo = __float2bfloat16_rn(v - __bfloat162float(h));
    g_Wth[idx] = __bfloat16_as_ushort(h);
    g_Wtl[idx] = __bfloat16_as_ushort(lo);
}

// ---------------- aggregation -> bf16 hi/lo row-major; block 0 zeroes g_stats ----------------
__global__ void k_agg(const float* __restrict__ Xext, const float* __restrict__ geps, int l) {
    if (blockIdx.x == 0 && threadIdx.x < 2 * DIM) g_stats[threadIdx.x] = 0.0f;
    int gt = blockIdx.x * blockDim.x + threadIdx.x;
    int node = gt >> 5;
    int lane = gt & 31;
    if (node >= NN) return;
    const float4* Xv = (Xext != nullptr) ? (const float4*)Xext : (const float4*)g_X;
    float a0 = 0.f, a1 = 0.f, a2 = 0.f, a3 = 0.f;
    int b = g_rowptr[node], e = g_rowptr[node + 1];
    for (int p = b; p < e; p++) {
        int s0 = __ldg(&g_col[p]);
        float4 v0 = __ldg(&Xv[(size_t)s0 * 32 + lane]);
        a0 += v0.x; a1 += v0.y; a2 += v0.z; a3 += v0.w;
    }
    float epsv = 1.0f + __ldg(&geps[l]);
    float4 xv = __ldg(&Xv[(size_t)node * 32 + lane]);
    float o[4];
    o[0] = fmaf(epsv, xv.x, a0);
    o[1] = fmaf(epsv, xv.y, a1);
    o[2] = fmaf(epsv, xv.z, a2);
    o[3] = fmaf(epsv, xv.w, a3);
    unsigned short hu[4], lu[4];
#pragma unroll
    for (int j = 0; j < 4; j++) {
        __nv_bfloat16 h = __float2bfloat16_rn(o[j]);
        __nv_bfloat16 lo = __float2bfloat16_rn(o[j] - __bfloat162float(h));
        hu[j] = __bfloat16_as_ushort(h);
        lu[j] = __bfloat16_as_ushort(lo);
    }
    size_t off = (size_t)node * DIM + lane * 4;
    *(uint2*)(g_Hh + off) = make_uint2((uint32_t)hu[0] | ((uint32_t)hu[1] << 16),
                                       (uint32_t)hu[2] | ((uint32_t)hu[3] << 16));
    *(uint2*)(g_Hl + off) = make_uint2((uint32_t)lu[0] | ((uint32_t)lu[1] << 16),
                                       (uint32_t)lu[2] | ((uint32_t)lu[3] << 16));
}

// ---------------- persistent tensor-core GEMM, direct-fragment epilogues ----------------
// MODE 1: A from g_Hh/g_Hl (cp.async, prefetched across tiles);
//         Y = A @ W1 + b -> g_Y (direct float2 stores); BN col stats -> g_stats (shfl+REDG)
// MODE 2: bnsc computed per-CTA from g_stats; A = relu(bn(g_Y)) (loader);
//         X = leaky(LN(A @ W2 + b)) -> g_X (direct float2 stores)
template <int MODE>
__global__ void __launch_bounds__(256, 2) k_gemm_mma(
    int mat, const float* __restrict__ bias,
    const float* __restrict__ bng, const float* __restrict__ bnb,
    const float* __restrict__ lng, const float* __restrict__ lnb)
{
    extern __shared__ unsigned char dyn[];
    __shared__ float s_bias[DIM];
    __shared__ float s_lg[DIM], s_lb[DIM];
    __shared__ float s_bsc[DIM], s_bsh[DIM];   // MODE2: bn scale/shift
    __shared__ float2 s_row[MT][4];
    __shared__ float2 s_ln[MT];

    int t = threadIdx.x;
    int w = t >> 5, lane = t & 31;
    int wr = w & 1, wc = w >> 1;          // wr: 32-row half, wc: 32-col group
    uint32_t sbase = smem_u32(dyn);

    // ---- one-time: persistent B tiles + params ----
    {
        const float4* sh = (const float4*)(g_Wth + (size_t)mat * DIM * DIM);
        const float4* sl = (const float4*)(g_Wtl + (size_t)mat * DIM * DIM);
#pragma unroll
        for (int j = 0; j < 8; j++) {
            int i = t + 256 * j;
            uint32_t d = (uint32_t)(i >> 4) * ROWB + (uint32_t)(i & 15) * 16;
            cpa16(sbase + SB_HI + d, sh + i);
            cpa16(sbase + SB_LO + d, sl + i);
        }
        CP_COMMIT();
    }
    if (t < DIM) {
        s_bias[t] = bias[t];
        if (MODE == 2) {
            s_lg[t] = lng[t];
            s_lb[t] = lnb[t];
            float mean = g_stats[t] * (1.0f / NN);
            float var  = g_stats[DIM + t] * (1.0f / NN) - mean * mean;
            float sc = bng[t] * rsqrtf(var + 1e-5f);
            s_bsc[t] = sc;
            s_bsh[t] = bnb[t] - mean * sc;
        }
    }
    CP_WAIT0();
    __syncthreads();

    // lane-invariant ldmatrix bases
    int grp = lane >> 3, lrow = lane & 7;
    uint32_t aBase[2];
#pragma unroll
    for (int mt = 0; mt < 2; mt++)
        aBase[mt] = sbase + SA_HI +
                    (uint32_t)(wr * 32 + mt * 16 + (grp & 1) * 8 + lrow) * ROWB +
                    (uint32_t)(grp >> 1) * 16;
    uint32_t bBase[2];
#pragma unroll
    for (int np = 0; np < 2; np++)
        bBase[np] = sbase + SB_HI +
                    (uint32_t)(wc * 32 + np * 16 + (grp >> 1) * 8 + lrow) * ROWB +
                    (uint32_t)(grp & 1) * 16;
    int fr = lane >> 2;                   // fragment row 0..7
    int fc = (lane & 3) * 2;              // fragment col pair

    if (MODE == 1) {
        // prefetch first tile's A
        {
            int bb = blockIdx.x;
            const float4* sh = (const float4*)(g_Hh + (size_t)bb * MT * DIM);
            const float4* sl = (const float4*)(g_Hl + (size_t)bb * MT * DIM);
            int nf4 = min(MT, NN - bb * MT) * 16;
#pragma unroll
            for (int j = 0; j < 4; j++) {
                int i = t + 256 * j;
                uint32_t d = (uint32_t)(i >> 4) * ROWB + (uint32_t)(i & 15) * 16;
                int ok = (i < nf4);
                cpa16z(sbase + SA_HI + d, sh + (ok ? i : 0), ok ? 16 : 0);
                cpa16z(sbase + SA_LO + d, sl + (ok ? i : 0), ok ? 16 : 0);
            }
            CP_COMMIT();
        }
        for (int b = blockIdx.x; b < NBLK2; b += GGRID) {
            int valid = min(MT, NN - b * MT);
            CP_WAIT0();
            __syncthreads();

            float acc[2][4][4];
#pragma unroll
            for (int mt = 0; mt < 2; mt++)
#pragma unroll
                for (int nt = 0; nt < 4; nt++)
#pragma unroll
                    for (int x = 0; x < 4; x++) acc[mt][nt][x] = 0.f;
#pragma unroll
            for (int kc = 0; kc < 8; kc++) {
                uint32_t aH[2][4], aL[2][4], bH[2][4], bL[2][4];
#pragma unroll
                for (int mt = 0; mt < 2; mt++) {
                    uint32_t ad = aBase[mt] + kc * 32;
                    ldm4(aH[mt], ad);
                    ldm4(aL[mt], ad + (SA_LO - SA_HI));
                }
#pragma unroll
                for (int np = 0; np < 2; np++) {
                    uint32_t bd = bBase[np] + kc * 32;
                    ldm4(bH[np], bd);
                    ldm4(bL[np], bd + (SB_LO - SB_HI));
                }
#pragma unroll
                for (int mt = 0; mt < 2; mt++)
#pragma unroll
                    for (int nt = 0; nt < 4; nt++) {
                        const uint32_t* bh = &bH[nt >> 1][(nt & 1) * 2];
                        const uint32_t* bl = &bL[nt >> 1][(nt & 1) * 2];
                        mma_bf16(acc[mt][nt], aH[mt], bh);
                        mma_bf16(acc[mt][nt], aH[mt], bl);
                        mma_bf16(acc[mt][nt], aL[mt], bh);
                    }
            }
            __syncthreads();   // all ldmatrix done -> safe to overwrite A

            // prefetch next tile's A (overlaps epilogue)
            int nb = b + GGRID;
            if (nb < NBLK2) {
                const float4* sh = (const float4*)(g_Hh + (size_t)nb * MT * DIM);
                const float4* sl = (const float4*)(g_Hl + (size_t)nb * MT * DIM);
                int nf4 = min(MT, NN - nb * MT) * 16;
#pragma unroll
                for (int j = 0; j < 4; j++) {
                    int i = t + 256 * j;
                    uint32_t d = (uint32_t)(i >> 4) * ROWB + (uint32_t)(i & 15) * 16;
                    int ok = (i < nf4);
                    cpa16z(sbase + SA_HI + d, sh + (ok ? i : 0), ok ? 16 : 0);
                    cpa16z(sbase + SA_LO + d, sl + (ok ? i : 0), ok ? 16 : 0);
                }
                CP_COMMIT();
            }

            // ---- direct epilogue: store Y + BN col stats ----
            float cs[4][2], cq[4][2];
#pragma unroll
            for (int nt = 0; nt < 4; nt++) {
                cs[nt][0] = cs[nt][1] = 0.f;
                cq[nt][0] = cq[nt][1] = 0.f;
            }
#pragma unroll
            for (int mt = 0; mt < 2; mt++) {
#pragma unroll
                for (int nt = 0; nt < 4; nt++) {
                    int row = wr * 32 + mt * 16 + fr;
                    int col = wc * 32 + nt * 8 + fc;
                    float b0 = s_bias[col], b1 = s_bias[col + 1];
                    float y0 = acc[mt][nt][0] + b0, y1 = acc[mt][nt][1] + b1;
                    float y2 = acc[mt][nt][2] + b0, y3 = acc[mt][nt][3] + b1;
                    if (row < valid) {
                        ((float2*)g_Y)[(size_t)(b * MT + row) * 64 + (col >> 1)] =
                            make_float2(y0, y1);
                        cs[nt][0] += y0; cq[nt][0] += y0 * y0;
                        cs[nt][1] += y1; cq[nt][1] += y1 * y1;
                    }
                    if (row + 8 < valid) {
                        ((float2*)g_Y)[(size_t)(b * MT + row + 8) * 64 + (col >> 1)] =
                            make_float2(y2, y3);
                        cs[nt][0] += y2; cq[nt][0] += y2 * y2;
                        cs[nt][1] += y3; cq[nt][1] += y3 * y3;
                    }
                }
            }
#pragma unroll
            for (int nt = 0; nt < 4; nt++)
#pragma unroll
                for (int j = 0; j < 2; j++) {
#pragma unroll
                    for (int m = 4; m <= 16; m <<= 1) {
                        cs[nt][j] += __shfl_xor_sync(0xFFFFFFFF, cs[nt][j], m);
                        cq[nt][j] += __shfl_xor_sync(0xFFFFFFFF, cq[nt][j], m);
                    }
                }
            if (fr == 0) {   // lanes 0..3
#pragma unroll
                for (int nt = 0; nt < 4; nt++) {
                    int col = wc * 32 + nt * 8 + fc;
                    atomicAdd(&g_stats[col],     cs[nt][0]);
                    atomicAdd(&g_stats[col + 1], cs[nt][1]);
                    atomicAdd(&g_stats[DIM + col],     cq[nt][0]);
                    atomicAdd(&g_stats[DIM + col + 1], cq[nt][1]);
                }
            }
        }
    } else {
        for (int b = blockIdx.x; b < NBLK2; b += GGRID) {
            int valid = min(MT, NN - b * MT);
            // ---- A prep: relu(bn(Y)) -> bf16 split -> smem ----
#pragma unroll
            for (int j = 0; j < 8; j++) {
                int q = t + 256 * j;
                int r = q >> 5, k4 = q & 31, k = k4 * 4;
                float v[4] = {0.f, 0.f, 0.f, 0.f};
                if (r < valid) {
                    float4 y = ((const float4*)g_Y)[(size_t)(b * MT + r) * 32 + k4];
                    v[0] = fmaxf(fmaf(y.x, s_bsc[k + 0], s_bsh[k + 0]), 0.f);
                    v[1] = fmaxf(fmaf(y.y, s_bsc[k + 1], s_bsh[k + 1]), 0.f);
                    v[2] = fmaxf(fmaf(y.z, s_bsc[k + 2], s_bsh[k + 2]), 0.f);
                    v[3] = fmaxf(fmaf(y.w, s_bsc[k + 3], s_bsh[k + 3]), 0.f);
                }
                unsigned short hu[4], lu[4];
#pragma unroll
                for (int x = 0; x < 4; x++) {
                    __nv_bfloat16 h = __float2bfloat16_rn(v[x]);
                    __nv_bfloat16 lo = __float2bfloat16_rn(v[x] - __bfloat162float(h));
                    hu[x] = __bfloat16_as_ushort(h);
                    lu[x] = __bfloat16_as_ushort(lo);
                }
                uint32_t d = (uint32_t)r * ROWB + (uint32_t)k * 2;
                *(uint2*)(dyn + SA_HI + d) = make_uint2((uint32_t)hu[0] | ((uint32_t)hu[1] << 16),
                                                        (uint32_t)hu[2] | ((uint32_t)hu[3] << 16));
                *(uint2*)(dyn + SA_LO + d) = make_uint2((uint32_t)lu[0] | ((uint32_t)lu[1] << 16),
                                                        (uint32_t)lu[2] | ((uint32_t)lu[3] << 16));
            }
            __syncthreads();

            float acc[2][4][4];
#pragma unroll
            for (int mt = 0; mt < 2; mt++)
#pragma unroll
                for (int nt = 0; nt < 4; nt++)
#pragma unroll
                    for (int x = 0; x < 4; x++) acc[mt][nt][x] = 0.f;
#pragma unroll
            for (int kc = 0; kc < 8; kc++) {
                uint32_t aH[2][4], aL[2][4], bH[2][4], bL[2][4];
#pragma unroll
                for (int mt = 0; mt < 2; mt++) {
                    uint32_t ad = aBase[mt] + kc * 32;
                    ldm4(aH[mt], ad);
                    ldm4(aL[mt], ad + (SA_LO - SA_HI));
                }
#pragma unroll
                for (int np = 0; np < 2; np++) {
                    uint32_t bd = bBase[np] + kc * 32;
                    ldm4(bH[np], bd);
                    ldm4(bL[np], bd + (SB_LO - SB_HI));
                }
#pragma unroll
                for (int mt = 0; mt < 2; mt++)
#pragma unroll
                    for (int nt = 0; nt < 4; nt++) {
                        const uint32_t* bh = &bH[nt >> 1][(nt & 1) * 2];
                        const uint32_t* bl = &bL[nt >> 1][(nt & 1) * 2];
                        mma_bf16(acc[mt][nt], aH[mt], bh);
                        mma_bf16(acc[mt][nt], aH[mt], bl);
                        mma_bf16(acc[mt][nt], aL[mt], bh);
                    }
            }

            // ---- direct LN epilogue ----
            // add bias in place; row partial sums over this warp's 8 cols
            float rs[2][2], rq[2][2];
#pragma unroll
            for (int mt = 0; mt < 2; mt++) {
                rs[mt][0] = rs[mt][1] = 0.f;
                rq[mt][0] = rq[mt][1] = 0.f;
#pragma unroll
                for (int nt = 0; nt < 4; nt++) {
                    int col = wc * 32 + nt * 8 + fc;
                    float b0 = s_bias[col], b1 = s_bias[col + 1];
                    acc[mt][nt][0] += b0; acc[mt][nt][1] += b1;
                    acc[mt][nt][2] += b0; acc[mt][nt][3] += b1;
                    rs[mt][0] += acc[mt][nt][0] + acc[mt][nt][1];
                    rq[mt][0] += acc[mt][nt][0] * acc[mt][nt][0] + acc[mt][nt][1] * acc[mt][nt][1];
                    rs[mt][1] += acc[mt][nt][2] + acc[mt][nt][3];
                    rq[mt][1] += acc[mt][nt][2] * acc[mt][nt][2] + acc[mt][nt][3] * acc[mt][nt][3];
                }
#pragma unroll
                for (int m = 1; m <= 2; m <<= 1) {
                    rs[mt][0] += __shfl_xor_sync(0xFFFFFFFF, rs[mt][0], m);
                    rq[mt][0] += __shfl_xor_sync(0xFFFFFFFF, rq[mt][0], m);
                    rs[mt][1] += __shfl_xor_sync(0xFFFFFFFF, rs[mt][1], m);
                    rq[mt][1] += __shfl_xor_sync(0xFFFFFFFF, rq[mt][1], m);
                }
            }
            if ((lane & 3) == 0) {
#pragma unroll
                for (int mt = 0; mt < 2; mt++) {
                    int row = wr * 32 + mt * 16 + fr;
                    s_row[row][wc]     = make_float2(rs[mt][0], rq[mt][0]);
                    s_row[row + 8][wc] = make_float2(rs[mt][1], rq[mt][1]);
                }
            }
            __syncthreads();
            if (t < MT) {
                float s = 0.f, ss = 0.f;
#pragma unroll
                for (int q = 0; q < 4; q++) {
                    float2 r = s_row[t][q];
                    s += r.x; ss += r.y;
                }
                float m = s * (1.0f / DIM);
                float vv = ss * (1.0f / DIM) - m * m;
                s_ln[t] = make_float2(m, rsqrtf(vv + 1e-5f));
            }
            __syncthreads();
#pragma unroll
            for (int mt = 0; mt < 2; mt++) {
                int row = wr * 32 + mt * 16 + fr;
                float2 p0 = s_ln[row];
                float2 p1 = s_ln[row + 8];
#pragma unroll
                for (int nt = 0; nt < 4; nt++) {
                    int col = wc * 32 + nt * 8 + fc;
                    float lg0 = s_lg[col], lg1 = s_lg[col + 1];
                    float lb0 = s_lb[col], lb1 = s_lb[col + 1];
                    if (row < valid) {
                        float y0 = (acc[mt][nt][0] - p0.x) * p0.y * lg0 + lb0;
                        float y1 = (acc[mt][nt][1] - p0.x) * p0.y * lg1 + lb1;
                        y0 = (y0 >= 0.f) ? y0 : 0.1f * y0;
                        y1 = (y1 >= 0.f) ? y1 : 0.1f * y1;
                        ((float2*)g_X)[(size_t)(b * MT + row) * 64 + (col >> 1)] =
                            make_float2(y0, y1);
                    }
                    if (row + 8 < valid) {
                        float y2 = (acc[mt][nt][2] - p1.x) * p1.y * lg0 + lb0;
                        float y3 = (acc[mt][nt][3] - p1.x) * p1.y * lg1 + lb1;
                        y2 = (y2 >= 0.f) ? y2 : 0.1f * y2;
                        y3 = (y3 >= 0.f) ? y3 : 0.1f * y3;
                        ((float2*)g_X)[(size_t)(b * MT + row + 8) * 64 + (col >> 1)] =
                            make_float2(y2, y3);
                    }
                }
            }
        }
    }
}

// ---------------- pooling ----------------
__global__ void k_bounds(const int* __restrict__ batch) {
    int g = blockIdx.x * blockDim.x + threadIdx.x;
    if (g > NG) return;
    int lo = 0, hi = NN;
    while (lo < hi) {
        int mid = (lo + hi) >> 1;
        if (batch[mid] < g) lo = mid + 1; else hi = mid;
    }
    g_gstart[g] = lo;
}
__global__ void k_pool() {
    int g = blockIdx.x;
    int t = threadIdx.x;
    int s = g_gstart[g], e = g_gstart[g + 1];
    float mx = -INFINITY, sum = 0.f;
    for (int n = s; n < e; n++) {
        float v = g_X[(size_t)n * DIM + t];
        mx = fmaxf(mx, v);
        sum += v;
    }
    float cnt = (float)(e - s);
    g_pool[(size_t)g * 2 * DIM + t]       = mx;
    g_pool[(size_t)g * 2 * DIM + DIM + t] = sum / fmaxf(cnt, 1.0f);
}
__global__ void k_out(const float* __restrict__ Wout, const float* __restrict__ bout,
                      float* __restrict__ out) {
    __shared__ float p[2 * DIM];
    int g = blockIdx.x;
    int t = threadIdx.x;
    p[t]       = g_pool[(size_t)g * 2 * DIM + t];
    p[t + DIM] = g_pool[(size_t)g * 2 * DIM + DIM + t];
    __syncthreads();
    float acc = bout[t];
#pragma unroll 8
    for (int k = 0; k < 2 * DIM; k++)
        acc = fmaf(p[k], Wout[(size_t)k * DIM + t], acc);
    out[(size_t)g * DIM + t] = acc;
}

// ---------------- launch ----------------
extern "C" void kernel_launch(void* const* d_in, const int* in_sizes, int n_in,
                              void* d_out, int out_size) {
    const float* x    = (const float*)d_in[0];
    const float* W1   = (const float*)d_in[1];
    const float* b1   = (const float*)d_in[2];
    const float* bn_g = (const float*)d_in[3];
    const float* bn_b = (const float*)d_in[4];
    const float* W2   = (const float*)d_in[5];
    const float* b2   = (const float*)d_in[6];
    const float* geps = (const float*)d_in[7];
    const float* ln_g = (const float*)d_in[8];
    const float* ln_b = (const float*)d_in[9];
    const float* Wout = (const float*)d_in[10];
    const float* bout = (const float*)d_in[11];
    const int* ei    = (const int*)d_in[12];
    const int* batch = (const int*)d_in[13];
    float* out = (float*)d_out;

    cudaFuncSetAttribute(k_gemm_mma<1>, cudaFuncAttributeMaxDynamicSharedMemorySize, DSMEM);
    cudaFuncSetAttribute(k_gemm_mma<2>, cudaFuncAttributeMaxDynamicSharedMemorySize, DSMEM);

    k_zero_csr<<<(NN + 255) / 256, 256>>>();
    k_hist<<<(NE + 255) / 256, 256>>>(ei);
    k_scan<<<1, 1024>>>();
    k_fill<<<(NE + 255) / 256, 256>>>(ei);
    k_wsplit<<<(6 * DIM * DIM + 255) / 256, 256>>>(W1, W2);

    for (int l = 0; l < NL; l++) {
        const float* in = (l == 0) ? x : nullptr;   // nullptr -> read g_X
        k_agg<<<(NN * 32 + 255) / 256, 256>>>(in, geps, l);
        k_gemm_mma<1><<<GGRID, 256, DSMEM>>>(2 * l, b1 + (size_t)l * DIM,
                                             0, 0, 0, 0);
        k_gemm_mma<2><<<GGRID, 256, DSMEM>>>(2 * l + 1, b2 + (size_t)l * DIM,
                                             bn_g + (size_t)l * DIM, bn_b + (size_t)l * DIM,
                                             ln_g + (size_t)l * DIM, ln_b + (size_t)l * DIM);
    }

    k_bounds<<<2, 256>>>(batch);
    k_pool<<<NG, DIM>>>();
    k_out<<<NG, DIM>>>(Wout, bout, out);
}

// round 17
// speedup vs baseline: 1.1511x; 1.1511x over previous
#include <cuda_runtime.h>
#include <cuda_bf16.h>
#include <stdint.h>
#include <math.h>
#include <float.h>

#define NN 100000
#define NE 1600000
#define DIM 128
#define NL 3
#define NG 256
#define MT 64                            // GEMM M-tile rows
#define NBLK2 ((NN + MT - 1) / MT)       // 1563
#define GGRID 296                        // persistent GEMM grid: 2 CTAs/SM x 148

// padded smem rows: 272 bytes (136 bf16)
#define ROWB 272
#define SB_HI 0                          // B hi/lo: persistent, 68KB
#define SB_LO 34816
#define SA_HI 69632                      // A hi/lo: per-tile, 34KB; reused as epilogue stage
#define SA_LO 87040
#define DSMEM 104448                     // 2 CTAs/SM

// ---------------- scratch (static device globals; zero-initialized) ----------------
__device__ __align__(16) float g_X[(size_t)NN * DIM];                 // layer output fp32
__device__ __align__(16) float g_Y[(size_t)NN * DIM];                 // post-GEMM1 pre-BN fp32
__device__ __align__(16) unsigned short g_Hh[(size_t)NN * DIM];       // agg bf16 hi, row-major
__device__ __align__(16) unsigned short g_Hl[(size_t)NN * DIM];       // agg bf16 lo
__device__ __align__(16) unsigned short g_Wth[6 * DIM * DIM];         // W^T bf16 hi [mat][n][k]
__device__ __align__(16) unsigned short g_Wtl[6 * DIM * DIM];
__device__ int   g_rowptr[NN + 1];
__device__ int   g_deg[NN];
__device__ int   g_cur[NN];
__device__ int   g_col[NE];
__device__ float g_stats[2 * DIM];       // zeroed by k_agg block 0 before each GEMM1
__device__ __align__(16) float g_pool[NG * 2 * DIM];
__device__ int   g_gstart[NG + 1];

__device__ __forceinline__ uint32_t smem_u32(const void* p) {
    uint32_t a;
    asm("{ .reg .u64 t; cvta.to.shared.u64 t, %1; cvt.u32.u64 %0, t; }" : "=r"(a) : "l"(p));
    return a;
}
__device__ __forceinline__ void ldm4(uint32_t* r, uint32_t a) {
    asm volatile("ldmatrix.sync.aligned.m8n8.x4.shared.b16 {%0,%1,%2,%3}, [%4];"
                 : "=r"(r[0]), "=r"(r[1]), "=r"(r[2]), "=r"(r[3]) : "r"(a));
}
__device__ __forceinline__ void mma_bf16(float* c, const uint32_t* a, const uint32_t* b) {
    asm volatile(
        "mma.sync.aligned.m16n8k16.row.col.f32.bf16.bf16.f32 "
        "{%0,%1,%2,%3}, {%4,%5,%6,%7}, {%8,%9}, {%0,%1,%2,%3};"
        : "+f"(c[0]), "+f"(c[1]), "+f"(c[2]), "+f"(c[3])
        : "r"(a[0]), "r"(a[1]), "r"(a[2]), "r"(a[3]), "r"(b[0]), "r"(b[1]));
}
__device__ __forceinline__ void cpa16(uint32_t dst, const void* src) {
    asm volatile("cp.async.cg.shared.global [%0], [%1], 16;" :: "r"(dst), "l"(src));
}
__device__ __forceinline__ void cpa16z(uint32_t dst, const void* src, int sz) {
    asm volatile("cp.async.cg.shared.global [%0], [%1], 16, %2;" :: "r"(dst), "l"(src), "r"(sz));
}
#define CP_WAIT_ALL() asm volatile("cp.async.commit_group;\ncp.async.wait_group 0;" ::: "memory")

// ---------------- CSR build ----------------
__global__ void k_zero_csr() {
    int i = blockIdx.x * blockDim.x + threadIdx.x;
    if (i < NN) { g_deg[i] = 0; g_cur[i] = 0; }
}
__global__ void k_hist(const int* __restrict__ ei) {
    int e = blockIdx.x * blockDim.x + threadIdx.x;
    if (e < NE) atomicAdd(&g_deg[ei[NE + e]], 1);
}
__global__ void k_scan() {
    __shared__ int part[1024];
    int t = threadIdx.x;
    const int C = (NN + 1023) / 1024;
    int beg = t * C, end = min(beg + C, NN);
    int s = 0;
    for (int i = beg; i < end; i++) s += g_deg[i];
    part[t] = s;
    __syncthreads();
    for (int d = 1; d < 1024; d <<= 1) {
        int v = (t >= d) ? part[t - d] : 0;
        __syncthreads();
        part[t] += v;
        __syncthreads();
    }
    int off = (t == 0) ? 0 : part[t - 1];
    for (int i = beg; i < end; i++) { g_rowptr[i] = off; off += g_deg[i]; }
    if (t == 1023) g_rowptr[NN] = part[1023];
}
__global__ void k_fill(const int* __restrict__ ei) {
    int e = blockIdx.x * blockDim.x + threadIdx.x;
    if (e < NE) {
        int s = ei[e];
        int d = ei[NE + e];
        g_col[g_rowptr[d] + atomicAdd(&g_cur[d], 1)] = s;
    }
}

// ---------------- weight split: W^T -> bf16 hi/lo row-major [n][k] ----------------
__global__ void k_wsplit(const float* __restrict__ W1, const float* __restrict__ W2) {
    int idx = blockIdx.x * blockDim.x + threadIdx.x;
    if (idx >= 6 * DIM * DIM) return;
    int mat = idx >> 14;
    int e = idx & 16383;
    int n = e >> 7, k = e & 127;
    int l = mat >> 1;
    const float* W = (mat & 1) ? W2 : W1;
    float v = W[(size_t)l * DIM * DIM + k * DIM + n];   // B[n][k] = W[k][n]
    __nv_bfloat16 h = __float2bfloat16_rn(v);
    __nv_bfloat16 lo = __float2bfloat16_rn(v - __bfloat162float(h));
    g_Wth[idx] = __bfloat16_as_ushort(h);
    g_Wtl[idx] = __bfloat16_as_ushort(lo);
}

// ---------------- aggregation -> bf16 hi/lo row-major; block 0 zeroes g_stats ----------------
__global__ void k_agg(const float* __restrict__ Xext, const float* __restrict__ geps, int l) {
    if (blockIdx.x == 0 && threadIdx.x < 2 * DIM) g_stats[threadIdx.x] = 0.0f;
    int gt = blockIdx.x * blockDim.x + threadIdx.x;
    int node = gt >> 5;
    int lane = gt & 31;
    if (node >= NN) return;
    const float4* Xv = (Xext != nullptr) ? (const float4*)Xext : (const float4*)g_X;
    float a0 = 0.f, a1 = 0.f, a2 = 0.f, a3 = 0.f;
    int b = g_rowptr[node], e = g_rowptr[node + 1];
    for (int p = b; p < e; p++) {
        int s0 = __ldg(&g_col[p]);
        float4 v0 = __ldg(&Xv[(size_t)s0 * 32 + lane]);
        a0 += v0.x; a1 += v0.y; a2 += v0.z; a3 += v0.w;
    }
    float epsv = 1.0f + __ldg(&geps[l]);
    float4 xv = __ldg(&Xv[(size_t)node * 32 + lane]);
    float o[4];
    o[0] = fmaf(epsv, xv.x, a0);
    o[1] = fmaf(epsv, xv.y, a1);
    o[2] = fmaf(epsv, xv.z, a2);
    o[3] = fmaf(epsv, xv.w, a3);
    unsigned short hu[4], lu[4];
#pragma unroll
    for (int j = 0; j < 4; j++) {
        __nv_bfloat16 h = __float2bfloat16_rn(o[j]);
        __nv_bfloat16 lo = __float2bfloat16_rn(o[j] - __bfloat162float(h));
        hu[j] = __bfloat16_as_ushort(h);
        lu[j] = __bfloat16_as_ushort(lo);
    }
    size_t off = (size_t)node * DIM + lane * 4;
    *(uint2*)(g_Hh + off) = make_uint2((uint32_t)hu[0] | ((uint32_t)hu[1] << 16),
                                       (uint32_t)hu[2] | ((uint32_t)hu[3] << 16));
    *(uint2*)(g_Hl + off) = make_uint2((uint32_t)lu[0] | ((uint32_t)lu[1] << 16),
                                       (uint32_t)lu[2] | ((uint32_t)lu[3] << 16));
}

// ---------------- persistent tensor-core GEMM: B resident, stride loop over M-tiles ----------------
// MODE 1: A from g_Hh/g_Hl (cp.async); D = A @ W1 + b -> g_Y, BN col stats -> g_stats
// MODE 2: bnsc computed per-CTA from g_stats (kernel boundary = stats complete);
//         A = relu(bn(g_Y)) computed in regs; D = leaky(LN(A @ W2 + b)) -> g_X
template <int MODE>
__global__ void __launch_bounds__(256, 2) k_gemm_mma(
    int mat, const float* __restrict__ bias,
    const float* __restrict__ bng, const float* __restrict__ bnb,
    const float* __restrict__ lng, const float* __restrict__ lnb)
{
    extern __shared__ unsigned char dyn[];
    __shared__ float s_bias[DIM];
    __shared__ float s_lg[DIM], s_lb[DIM];
    __shared__ float s_bsc[DIM], s_bsh[DIM];
    __shared__ float2 s_half[MT][4];
    __shared__ float2 s_ln[MT];

    int t = threadIdx.x;
    int w = t >> 5, lane = t & 31;
    int wr = w & 1, wc = w >> 1;          // wr: 32-row half, wc: 32-col group
    uint32_t sbase = smem_u32(dyn);
    float* stage = (float*)(dyn + SA_HI); // stage reuses A region only (B stays resident)

    // ---- one-time: B tiles (persistent) + params ----
    {
        const float4* sh = (const float4*)(g_Wth + (size_t)mat * DIM * DIM);
        const float4* sl = (const float4*)(g_Wtl + (size_t)mat * DIM * DIM);
#pragma unroll
        for (int j = 0; j < 8; j++) {
            int i = t + 256 * j;
            uint32_t d = (uint32_t)(i >> 4) * ROWB + (uint32_t)(i & 15) * 16;
            cpa16(sbase + SB_HI + d, sh + i);
            cpa16(sbase + SB_LO + d, sl + i);
        }
    }
    if (t < DIM) {
        s_bias[t] = bias[t];
        if (MODE == 2) {
            s_lg[t] = lng[t];
            s_lb[t] = lnb[t];
            float mean = g_stats[t] * (1.0f / NN);
            float var  = g_stats[DIM + t] * (1.0f / NN) - mean * mean;
            float sc = bng[t] * rsqrtf(var + 1e-5f);
            s_bsc[t] = sc;
            s_bsh[t] = bnb[t] - mean * sc;
        }
    }
    CP_WAIT_ALL();
    __syncthreads();

    // lane-invariant ldmatrix bases
    int grp = lane >> 3, lrow = lane & 7;
    uint32_t aBase[2];
#pragma unroll
    for (int mt = 0; mt < 2; mt++)
        aBase[mt] = sbase + SA_HI +
                    (uint32_t)(wr * 32 + mt * 16 + (grp & 1) * 8 + lrow) * ROWB +
                    (uint32_t)(grp >> 1) * 16;
    uint32_t bBase[2];
#pragma unroll
    for (int np = 0; np < 2; np++)
        bBase[np] = sbase + SB_HI +
                    (uint32_t)(wc * 32 + np * 16 + (grp >> 1) * 8 + lrow) * ROWB +
                    (uint32_t)(grp & 1) * 16;
    int fr = lane >> 2;
    int fc = (lane & 3) * 2;

    // ---- persistent stride loop over M-tiles ----
    for (int b = blockIdx.x; b < NBLK2; b += GGRID) {
        int valid = min(MT, NN - b * MT);

        // ---- stage A ----
        if (MODE == 1) {
            const float4* sh = (const float4*)(g_Hh + (size_t)b * MT * DIM);
            const float4* sl = (const float4*)(g_Hl + (size_t)b * MT * DIM);
            int nf4 = valid * 16;
#pragma unroll
            for (int j = 0; j < 4; j++) {
                int i = t + 256 * j;
                uint32_t d = (uint32_t)(i >> 4) * ROWB + (uint32_t)(i & 15) * 16;
                int ok = (i < nf4);
                int is = ok ? i : 0;
                cpa16z(sbase + SA_HI + d, sh + is, ok ? 16 : 0);
                cpa16z(sbase + SA_LO + d, sl + is, ok ? 16 : 0);
            }
            CP_WAIT_ALL();
        } else {
#pragma unroll
            for (int j = 0; j < 8; j++) {
                int q = t + 256 * j;
                int r = q >> 5, k4 = q & 31, k = k4 * 4;
                float v[4] = {0.f, 0.f, 0.f, 0.f};
                if (r < valid) {
                    float4 y = ((const float4*)g_Y)[(size_t)(b * MT + r) * 32 + k4];
                    v[0] = fmaxf(fmaf(y.x, s_bsc[k + 0], s_bsh[k + 0]), 0.f);
                    v[1] = fmaxf(fmaf(y.y, s_bsc[k + 1], s_bsh[k + 1]), 0.f);
                    v[2] = fmaxf(fmaf(y.z, s_bsc[k + 2], s_bsh[k + 2]), 0.f);
                    v[3] = fmaxf(fmaf(y.w, s_bsc[k + 3], s_bsh[k + 3]), 0.f);
                }
                unsigned short hu[4], lu[4];
#pragma unroll
                for (int x = 0; x < 4; x++) {
                    __nv_bfloat16 h = __float2bfloat16_rn(v[x]);
                    __nv_bfloat16 lo = __float2bfloat16_rn(v[x] - __bfloat162float(h));
                    hu[x] = __bfloat16_as_ushort(h);
                    lu[x] = __bfloat16_as_ushort(lo);
                }
                uint32_t d = (uint32_t)r * ROWB + (uint32_t)k * 2;
                *(uint2*)(dyn + SA_HI + d) = make_uint2((uint32_t)hu[0] | ((uint32_t)hu[1] << 16),
                                                        (uint32_t)hu[2] | ((uint32_t)hu[3] << 16));
                *(uint2*)(dyn + SA_LO + d) = make_uint2((uint32_t)lu[0] | ((uint32_t)lu[1] << 16),
                                                        (uint32_t)lu[2] | ((uint32_t)lu[3] << 16));
            }
        }
        __syncthreads();

        // ---- mma mainloop: acc[2][4][4] (32x32 per warp) ----
        float acc[2][4][4];
#pragma unroll
        for (int mt = 0; mt < 2; mt++)
#pragma unroll
            for (int nt = 0; nt < 4; nt++)
#pragma unroll
                for (int x = 0; x < 4; x++) acc[mt][nt][x] = 0.f;

#pragma unroll
        for (int kc = 0; kc < 8; kc++) {
            uint32_t aH[2][4], aL[2][4], bH[2][4], bL[2][4];
#pragma unroll
            for (int mt = 0; mt < 2; mt++) {
                uint32_t ad = aBase[mt] + kc * 32;
                ldm4(aH[mt], ad);
                ldm4(aL[mt], ad + (SA_LO - SA_HI));
            }
#pragma unroll
            for (int np = 0; np < 2; np++) {
                uint32_t bd = bBase[np] + kc * 32;
                ldm4(bH[np], bd);
                ldm4(bL[np], bd + (SB_LO - SB_HI));
            }
#pragma unroll
            for (int mt = 0; mt < 2; mt++)
#pragma unroll
                for (int nt = 0; nt < 4; nt++) {
                    const uint32_t* bh = &bH[nt >> 1][(nt & 1) * 2];
                    const uint32_t* bl = &bL[nt >> 1][(nt & 1) * 2];
                    mma_bf16(acc[mt][nt], aH[mt], bh);
                    mma_bf16(acc[mt][nt], aH[mt], bl);
                    mma_bf16(acc[mt][nt], aL[mt], bh);
                }
        }
        __syncthreads();   // A smem dead -> reuse as stage (B untouched)

        // ---- stage accumulators (+bias) into A region ----
#pragma unroll
        for (int mt = 0; mt < 2; mt++) {
#pragma unroll
            for (int nt = 0; nt < 4; nt++) {
                int row = wr * 32 + mt * 16 + fr;
                int col = wc * 32 + nt * 8 + fc;
                float b0 = s_bias[col], b1 = s_bias[col + 1];
                *(float2*)&stage[row * 132 + col] =
                    make_float2(acc[mt][nt][0] + b0, acc[mt][nt][1] + b1);
                *(float2*)&stage[(row + 8) * 132 + col] =
                    make_float2(acc[mt][nt][2] + b0, acc[mt][nt][3] + b1);
            }
        }
        __syncthreads();

        if (MODE == 1) {
            int col = t & 127;
            int rs = (t >> 7) * 32;
            int re = min(rs + 32, valid);
            float s = 0.f, ss = 0.f;
            for (int r = rs; r < re; r++) {
                float x = stage[r * 132 + col];
                s += x; ss += x * x;
            }
            atomicAdd(&g_stats[col], s);
            atomicAdd(&g_stats[DIM + col], ss);
#pragma unroll
            for (int j = 0; j < 8; j++) {
                int q = t + 256 * j;
                int r = q >> 5, c4 = q & 31;
                if (r < valid) {
                    float4 o;
                    o.x = stage[r * 132 + c4 * 4 + 0];
                    o.y = stage[r * 132 + c4 * 4 + 1];
                    o.z = stage[r * 132 + c4 * 4 + 2];
                    o.w = stage[r * 132 + c4 * 4 + 3];
                    ((float4*)g_Y)[(size_t)(b * MT + r) * 32 + c4] = o;
                }
            }
        } else {
            {
                int row = t >> 2, q = t & 3;
                float s = 0.f, ss = 0.f;
                int c0 = q * 32;
                for (int c = c0; c < c0 + 32; c++) {
                    float x = stage[row * 132 + c];
                    s += x; ss += x * x;
                }
                s_half[row][q] = make_float2(s, ss);
            }
            __syncthreads();
            if (t < MT) {
                float s = 0.f, ss = 0.f;
#pragma unroll
                for (int q = 0; q < 4; q++) {
                    float2 r = s_half[t][q];
                    s += r.x; ss += r.y;
                }
                float m = s * (1.0f / DIM);
                float vv = ss * (1.0f / DIM) - m * m;
                s_ln[t] = make_float2(m, rsqrtf(vv + 1e-5f));
            }
            __syncthreads();
#pragma unroll
            for (int j = 0; j < 8; j++) {
                int q = t + 256 * j;
                int r = q >> 5, c4 = q & 31;
                if (r < valid) {
                    float2 p = s_ln[r];
                    float4 o;
                    float* src = &stage[r * 132 + c4 * 4];
                    float y0 = (src[0] - p.x) * p.y * s_lg[c4 * 4 + 0] + s_lb[c4 * 4 + 0];
                    float y1 = (src[1] - p.x) * p.y * s_lg[c4 * 4 + 1] + s_lb[c4 * 4 + 1];
                    float y2 = (src[2] - p.x) * p.y * s_lg[c4 * 4 + 2] + s_lb[c4 * 4 + 2];
                    float y3 = (src[3] - p.x) * p.y * s_lg[c4 * 4 + 3] + s_lb[c4 * 4 + 3];
                    o.x = (y0 >= 0.f) ? y0 : 0.1f * y0;
                    o.y = (y1 >= 0.f) ? y1 : 0.1f * y1;
                    o.z = (y2 >= 0.f) ? y2 : 0.1f * y2;
                    o.w = (y3 >= 0.f) ? y3 : 0.1f * y3;
                    ((float4*)g_X)[(size_t)(b * MT + r) * 32 + c4] = o;
                }
            }
        }
        __syncthreads();   // stage dead before next tile's A store
    }
}

// ---------------- pooling ----------------
__global__ void k_bounds(const int* __restrict__ batch) {
    int g = blockIdx.x * blockDim.x + threadIdx.x;
    if (g > NG) return;
    int lo = 0, hi = NN;
    while (lo < hi) {
        int mid = (lo + hi) >> 1;
        if (batch[mid] < g) lo = mid + 1; else hi = mid;
    }
    g_gstart[g] = lo;
}
__global__ void k_pool() {
    int g = blockIdx.x;
    int t = threadIdx.x;
    int s = g_gstart[g], e = g_gstart[g + 1];
    float mx = -INFINITY, sum = 0.f;
    for (int n = s; n < e; n++) {
        float v = g_X[(size_t)n * DIM + t];
        mx = fmaxf(mx, v);
        sum += v;
    }
    float cnt = (float)(e - s);
    g_pool[(size_t)g * 2 * DIM + t]       = mx;
    g_pool[(size_t)g * 2 * DIM + DIM + t] = sum / fmaxf(cnt, 1.0f);
}
__global__ void k_out(const float* __restrict__ Wout, const float* __restrict__ bout,
                      float* __restrict__ out) {
    __shared__ float p[2 * DIM];
    int g = blockIdx.x;
    int t = threadIdx.x;
    p[t]       = g_pool[(size_t)g * 2 * DIM + t];
    p[t + DIM] = g_pool[(size_t)g * 2 * DIM + DIM + t];
    __syncthreads();
    float acc = bout[t];
#pragma unroll 8
    for (int k = 0; k < 2 * DIM; k++)
        acc = fmaf(p[k], Wout[(size_t)k * DIM + t], acc);
    out[(size_t)g * DIM + t] = acc;
}

// ---------------- launch ----------------
extern "C" void kernel_launch(void* const* d_in, const int* in_sizes, int n_in,
                              void* d_out, int out_size) {
    const float* x    = (const float*)d_in[0];
    const float* W1   = (const float*)d_in[1];
    const float* b1   = (const float*)d_in[2];
    const float* bn_g = (const float*)d_in[3];
    const float* bn_b = (const float*)d_in[4];
    const float* W2   = (const float*)d_in[5];
    const float* b2   = (const float*)d_in[6];
    const float* geps = (const float*)d_in[7];
    const float* ln_g = (const float*)d_in[8];
    const float* ln_b = (const float*)d_in[9];
    const float* Wout = (const float*)d_in[10];
    const float* bout = (const float*)d_in[11];
    const int* ei    = (const int*)d_in[12];
    const int* batch = (const int*)d_in[13];
    float* out = (float*)d_out;

    cudaFuncSetAttribute(k_gemm_mma<1>, cudaFuncAttributeMaxDynamicSharedMemorySize, DSMEM);
    cudaFuncSetAttribute(k_gemm_mma<2>, cudaFuncAttributeMaxDynamicSharedMemorySize, DSMEM);

    k_zero_csr<<<(NN + 255) / 256, 256>>>();
    k_hist<<<(NE + 255) / 256, 256>>>(ei);
    k_scan<<<1, 1024>>>();
    k_fill<<<(NE + 255) / 256, 256>>>(ei);
    k_wsplit<<<(6 * DIM * DIM + 255) / 256, 256>>>(W1, W2);

    for (int l = 0; l < NL; l++) {
        const float* in = (l == 0) ? x : nullptr;   // nullptr -> read g_X
        k_agg<<<(NN * 32 + 255) / 256, 256>>>(in, geps, l);
        k_gemm_mma<1><<<GGRID, 256, DSMEM>>>(2 * l, b1 + (size_t)l * DIM,
                                             0, 0, 0, 0);
        k_gemm_mma<2><<<GGRID, 256, DSMEM>>>(2 * l + 1, b2 + (size_t)l * DIM,
                                             bn_g + (size_t)l * DIM, bn_b + (size_t)l * DIM,
                                             ln_g + (size_t)l * DIM, ln_b + (size_t)l * DIM);
    }

    k_bounds<<<2, 256>>>(batch);
    k_pool<<<NG, DIM>>>();
    k_out<<<NG, DIM>>>(Wout, bout, out);
}